// round 1
// baseline (speedup 1.0000x reference)
#include <cuda_runtime.h>
#include <cuda_bf16.h>
#include <math.h>

// Problem dims
#define BB 2
#define SS 2048
#define DD 1024
#define HH 16
#define DH 64
#define MTOT (BB*SS)        // 4096 rows

// ---------------- scratch (static device globals; no allocs) ----------------
__device__ float g_h   [(size_t)MTOT * DD];        // LN1 out, reused as LN2 out
__device__ float g_qkv [(size_t)MTOT * 3 * DD];    // qkv
__device__ float g_att [(size_t)MTOT * DD];        // attention merged output
__device__ float g_x1  [(size_t)MTOT * DD];        // residual after attention
__device__ float g_ff  [(size_t)MTOT * 4 * DD];    // GELU(mlp1) output

// ---------------- LayerNorm ----------------
__global__ void __launch_bounds__(256) ln_kernel(const float* __restrict__ x,
                                                 const float* __restrict__ g,
                                                 const float* __restrict__ b,
                                                 float* __restrict__ y) {
    int row = blockIdx.x;
    int tid = threadIdx.x;
    const float4* xr = (const float4*)(x + (size_t)row * DD);
    float4 v = xr[tid];
    float s  = v.x + v.y + v.z + v.w;
    float sq = v.x*v.x + v.y*v.y + v.z*v.z + v.w*v.w;
    #pragma unroll
    for (int off = 16; off > 0; off >>= 1) {
        s  += __shfl_xor_sync(0xffffffff, s,  off);
        sq += __shfl_xor_sync(0xffffffff, sq, off);
    }
    __shared__ float ss[8], ssq[8];
    __shared__ float smu, srstd;
    int wid = tid >> 5, lane = tid & 31;
    if (lane == 0) { ss[wid] = s; ssq[wid] = sq; }
    __syncthreads();
    if (tid == 0) {
        float t = 0.f, t2 = 0.f;
        #pragma unroll
        for (int w = 0; w < 8; ++w) { t += ss[w]; t2 += ssq[w]; }
        float mu  = t * (1.0f / DD);
        float var = t2 * (1.0f / DD) - mu * mu;
        smu = mu; srstd = rsqrtf(var + 1e-5f);
    }
    __syncthreads();
    float mu = smu, rstd = srstd;
    float4 gg = ((const float4*)g)[tid];
    float4 bb = ((const float4*)b)[tid];
    float4 o;
    o.x = (v.x - mu) * rstd * gg.x + bb.x;
    o.y = (v.y - mu) * rstd * gg.y + bb.y;
    o.z = (v.z - mu) * rstd * gg.z + bb.z;
    o.w = (v.w - mu) * rstd * gg.w + bb.w;
    ((float4*)(y + (size_t)row * DD))[tid] = o;
}

// ---------------- SGEMM 128x128x8, 256 thr, 8x8 micro-tile ----------------
// EPI: 0 = bias only, 1 = bias + residual, 2 = bias + exact GELU
template<int EPI>
__global__ void __launch_bounds__(256, 2) sgemm_kernel(const float* __restrict__ A,
                                                       const float* __restrict__ B,
                                                       const float* __restrict__ bias,
                                                       const float* __restrict__ res,
                                                       float* __restrict__ C,
                                                       int M, int N, int K) {
    __shared__ float sA[8][128];
    __shared__ float sB[8][128];
    int tid = threadIdx.x;
    int bx = blockIdx.x, by = blockIdx.y;

    int arow = tid >> 1, acol = (tid & 1) * 4;
    int brow = tid >> 5, bcol = (tid & 31) * 4;
    const float* Ag = A + (size_t)(by * 128 + arow) * K + acol;
    const float* Bg = B + (size_t)brow * N + bx * 128 + bcol;

    int trow = (tid >> 4) * 8, tcol = (tid & 15) * 8;
    float acc[8][8];
    #pragma unroll
    for (int i = 0; i < 8; i++)
        #pragma unroll
        for (int j = 0; j < 8; j++) acc[i][j] = 0.f;

    float4 an = *(const float4*)Ag;
    float4 bn = *(const float4*)Bg;

    for (int k0 = 0; k0 < K; k0 += 8) {
        sA[acol + 0][arow] = an.x;
        sA[acol + 1][arow] = an.y;
        sA[acol + 2][arow] = an.z;
        sA[acol + 3][arow] = an.w;
        *(float4*)&sB[brow][bcol] = bn;
        __syncthreads();
        if (k0 + 8 < K) {
            an = *(const float4*)(Ag + k0 + 8);
            bn = *(const float4*)(Bg + (size_t)(k0 + 8) * N);
        }
        #pragma unroll
        for (int kk = 0; kk < 8; ++kk) {
            float ra[8], rb[8];
            *(float4*)&ra[0] = *(const float4*)&sA[kk][trow];
            *(float4*)&ra[4] = *(const float4*)&sA[kk][trow + 4];
            *(float4*)&rb[0] = *(const float4*)&sB[kk][tcol];
            *(float4*)&rb[4] = *(const float4*)&sB[kk][tcol + 4];
            #pragma unroll
            for (int i = 0; i < 8; i++)
                #pragma unroll
                for (int j = 0; j < 8; j++)
                    acc[i][j] = fmaf(ra[i], rb[j], acc[i][j]);
        }
        __syncthreads();
    }

    #pragma unroll
    for (int i = 0; i < 8; i++) {
        int gm = by * 128 + trow + i;
        size_t rowoff = (size_t)gm * N + bx * 128;
        #pragma unroll
        for (int j = 0; j < 8; j++) {
            int gn = tcol + j;
            float v = acc[i][j] + bias[bx * 128 + gn];
            if (EPI == 1) v += res[rowoff + gn];
            if (EPI == 2) v = 0.5f * v * (1.0f + erff(v * 0.7071067811865475f));
            C[rowoff + gn] = v;
        }
    }
}

// ---------------- Flash attention (fp32, online softmax) ----------------
// grid: (S/64, B*H), 256 threads. qkv layout [B*S, 3*D], head h cols h*64..h*64+63
#define SLD 65
#define ATTN_SMEM ((4 * 64 * SLD + 3 * 64) * (int)sizeof(float))

__global__ void __launch_bounds__(256) attn_kernel(const float* __restrict__ qkv,
                                                   float* __restrict__ out) {
    extern __shared__ float sm[];
    float* sQ  = sm;
    float* sK  = sQ + 64 * SLD;
    float* sV  = sK + 64 * SLD;
    float* sS  = sV + 64 * SLD;
    float* sM  = sS + 64 * SLD;
    float* sL  = sM + 64;
    float* sAl = sL + 64;

    int tid = threadIdx.x;
    int qt = blockIdx.x, bh = blockIdx.y;
    int b = bh >> 4, h = bh & 15;
    const size_t rs = 3 * DD;

    size_t qbase = ((size_t)(b * SS + qt * 64)) * rs + h * DH;
    for (int i = tid; i < 4096; i += 256) {
        int r = i >> 6, c = i & 63;
        sQ[r * SLD + c] = qkv[qbase + (size_t)r * rs + c];
    }
    if (tid < 64) { sM[tid] = -1e30f; sL[tid] = 0.f; }

    int qb = tid >> 4, db = tid & 15;
    int q0 = qb * 4;
    float acc[4][4];
    #pragma unroll
    for (int i = 0; i < 4; i++)
        #pragma unroll
        for (int j = 0; j < 4; j++) acc[i][j] = 0.f;

    for (int kt = 0; kt < SS / 64; ++kt) {
        __syncthreads();  // protect sK/sV/sS from previous iteration readers
        size_t kbase = ((size_t)(b * SS + kt * 64)) * rs + h * DH;
        for (int i = tid; i < 4096; i += 256) {
            int r = i >> 6, c = i & 63;
            size_t g = kbase + (size_t)r * rs + c;
            sK[r * SLD + c] = qkv[g + DD];
            sV[r * SLD + c] = qkv[g + 2 * DD];
        }
        __syncthreads();

        // scores: 4 q-rows x 4 k-cols (k-cols interleaved db + j*16)
        float s[4][4];
        #pragma unroll
        for (int i = 0; i < 4; i++)
            #pragma unroll
            for (int j = 0; j < 4; j++) s[i][j] = 0.f;
        #pragma unroll 16
        for (int d = 0; d < 64; ++d) {
            float a0 = sQ[(q0 + 0) * SLD + d];
            float a1 = sQ[(q0 + 1) * SLD + d];
            float a2 = sQ[(q0 + 2) * SLD + d];
            float a3 = sQ[(q0 + 3) * SLD + d];
            #pragma unroll
            for (int j = 0; j < 4; j++) {
                float kv = sK[(db + j * 16) * SLD + d];
                s[0][j] = fmaf(a0, kv, s[0][j]);
                s[1][j] = fmaf(a1, kv, s[1][j]);
                s[2][j] = fmaf(a2, kv, s[2][j]);
                s[3][j] = fmaf(a3, kv, s[3][j]);
            }
        }
        #pragma unroll
        for (int i = 0; i < 4; i++)
            #pragma unroll
            for (int j = 0; j < 4; j++)
                sS[(q0 + i) * SLD + db + j * 16] = s[i][j] * 0.125f;
        __syncthreads();

        // row max / alpha
        if (tid < 64) {
            float mold = sM[tid], mt = -1e30f;
            const float* row = sS + tid * SLD;
            #pragma unroll 16
            for (int k = 0; k < 64; k++) mt = fmaxf(mt, row[k]);
            float mnew = fmaxf(mold, mt);
            sAl[tid] = __expf(mold - mnew);
            sM[tid]  = mnew;
        }
        __syncthreads();

        // exponentiate + rescale accumulators
        #pragma unroll
        for (int i = 0; i < 4; i++) {
            float mn = sM[q0 + i], al = sAl[q0 + i];
            #pragma unroll
            for (int j = 0; j < 4; j++) {
                int idx = (q0 + i) * SLD + db + j * 16;
                float p = __expf(sS[idx] - mn);
                sS[idx] = p;
                acc[i][j] *= al;
            }
        }
        __syncthreads();

        // l update (64 threads) + acc += P @ V (all threads)
        if (tid < 64) {
            float lsum = 0.f;
            const float* row = sS + tid * SLD;
            #pragma unroll 16
            for (int k = 0; k < 64; k++) lsum += row[k];
            sL[tid] = sL[tid] * sAl[tid] + lsum;
        }
        #pragma unroll 8
        for (int k = 0; k < 64; ++k) {
            float p0 = sS[(q0 + 0) * SLD + k];
            float p1 = sS[(q0 + 1) * SLD + k];
            float p2 = sS[(q0 + 2) * SLD + k];
            float p3 = sS[(q0 + 3) * SLD + k];
            #pragma unroll
            for (int j = 0; j < 4; j++) {
                float vv = sV[k * SLD + db + j * 16];
                acc[0][j] = fmaf(p0, vv, acc[0][j]);
                acc[1][j] = fmaf(p1, vv, acc[1][j]);
                acc[2][j] = fmaf(p2, vv, acc[2][j]);
                acc[3][j] = fmaf(p3, vv, acc[3][j]);
            }
        }
    }
    __syncthreads();

    size_t obase = ((size_t)(b * SS + qt * 64)) * DD + h * DH;
    #pragma unroll
    for (int i = 0; i < 4; i++) {
        float inv = 1.0f / sL[q0 + i];
        #pragma unroll
        for (int j = 0; j < 4; j++)
            out[obase + (size_t)(q0 + i) * DD + db + j * 16] = acc[i][j] * inv;
    }
}

// ---------------- launch ----------------
extern "C" void kernel_launch(void* const* d_in, const int* in_sizes, int n_in,
                              void* d_out, int out_size) {
    const float* x     = (const float*)d_in[0];
    const float* ln1_g = (const float*)d_in[1];
    const float* ln1_b = (const float*)d_in[2];
    const float* w_qkv = (const float*)d_in[3];
    const float* b_qkv = (const float*)d_in[4];
    const float* w_out = (const float*)d_in[5];
    const float* b_out = (const float*)d_in[6];
    const float* ln2_g = (const float*)d_in[7];
    const float* ln2_b = (const float*)d_in[8];
    const float* w1    = (const float*)d_in[9];
    const float* b1    = (const float*)d_in[10];
    const float* w2    = (const float*)d_in[11];
    const float* b2    = (const float*)d_in[12];
    float* out = (float*)d_out;

    float *h, *qkv, *att, *x1, *ff;
    cudaGetSymbolAddress((void**)&h,   g_h);
    cudaGetSymbolAddress((void**)&qkv, g_qkv);
    cudaGetSymbolAddress((void**)&att, g_att);
    cudaGetSymbolAddress((void**)&x1,  g_x1);
    cudaGetSymbolAddress((void**)&ff,  g_ff);

    cudaFuncSetAttribute(attn_kernel, cudaFuncAttributeMaxDynamicSharedMemorySize,
                         ATTN_SMEM);

    // LN1
    ln_kernel<<<MTOT, 256>>>(x, ln1_g, ln1_b, h);
    // QKV projection
    sgemm_kernel<0><<<dim3(3 * DD / 128, MTOT / 128), 256>>>(h, w_qkv, b_qkv, nullptr,
                                                             qkv, MTOT, 3 * DD, DD);
    // Attention
    attn_kernel<<<dim3(SS / 64, BB * HH), 256, ATTN_SMEM>>>(qkv, att);
    // Out projection + residual(x)
    sgemm_kernel<1><<<dim3(DD / 128, MTOT / 128), 256>>>(att, w_out, b_out, x,
                                                         x1, MTOT, DD, DD);
    // LN2
    ln_kernel<<<MTOT, 256>>>(x1, ln2_g, ln2_b, h);
    // MLP up + GELU
    sgemm_kernel<2><<<dim3(4 * DD / 128, MTOT / 128), 256>>>(h, w1, b1, nullptr,
                                                             ff, MTOT, 4 * DD, DD);
    // MLP down + residual(x1) -> final output
    sgemm_kernel<1><<<dim3(DD / 128, MTOT / 128), 256>>>(ff, w2, b2, x1,
                                                         out, MTOT, DD, 4 * DD);
}

// round 10
// speedup vs baseline: 1.7042x; 1.7042x over previous
#include <cuda_runtime.h>
#include <cuda_bf16.h>
#include <math.h>
#include <cstdint>

// Problem dims
#define BB 2
#define SS 2048
#define DD 1024
#define HH 16
#define DH 64
#define MTOT (BB*SS)        // 4096 rows

// ---------------- PTX helpers (sm_80-era only; no tcgen05) ----------------
__device__ __forceinline__ uint32_t smem_u32(const void* p) {
    uint32_t a;
    asm("{ .reg .u64 t; cvta.to.shared.u64 t, %1; cvt.u32.u64 %0, t; }" : "=r"(a) : "l"(p));
    return a;
}
#define CP16(sa, gp)  asm volatile("cp.async.cg.shared.global [%0], [%1], 16;" :: "r"(sa), "l"(gp))
#define CP_COMMIT()   asm volatile("cp.async.commit_group;" ::: "memory")
#define CP_WAIT1()    asm volatile("cp.async.wait_group 1;" ::: "memory")

#define LDSM4(r, addr) \
    asm volatile("ldmatrix.sync.aligned.m8n8.x4.shared.b16 {%0,%1,%2,%3}, [%4];" \
        : "=r"((r)[0]), "=r"((r)[1]), "=r"((r)[2]), "=r"((r)[3]) : "r"(addr))

#define MMA16816(d, a, b0, b1) \
    asm volatile("mma.sync.aligned.m16n8k16.row.col.f32.bf16.bf16.f32 " \
        "{%0,%1,%2,%3}, {%4,%5,%6,%7}, {%8,%9}, {%0,%1,%2,%3};" \
        : "+f"((d)[0]), "+f"((d)[1]), "+f"((d)[2]), "+f"((d)[3]) \
        : "r"((a)[0]), "r"((a)[1]), "r"((a)[2]), "r"((a)[3]), "r"(b0), "r"(b1))

// ---------------- scratch (static device globals; no allocs) ----------------
__device__ __nv_bfloat16 g_h_hi [(size_t)MTOT * DD];
__device__ __nv_bfloat16 g_h_lo [(size_t)MTOT * DD];
__device__ float         g_qkv  [(size_t)MTOT * 3 * DD];
__device__ __nv_bfloat16 g_att_hi[(size_t)MTOT * DD];
__device__ __nv_bfloat16 g_att_lo[(size_t)MTOT * DD];
__device__ float         g_x1   [(size_t)MTOT * DD];
__device__ __nv_bfloat16 g_ff_hi[(size_t)MTOT * 4 * DD];
__device__ __nv_bfloat16 g_ff_lo[(size_t)MTOT * 4 * DD];
__device__ __nv_bfloat16 g_wqkvT_hi[(size_t)3 * DD * DD];
__device__ __nv_bfloat16 g_wqkvT_lo[(size_t)3 * DD * DD];
__device__ __nv_bfloat16 g_woutT_hi[(size_t)DD * DD];
__device__ __nv_bfloat16 g_woutT_lo[(size_t)DD * DD];
__device__ __nv_bfloat16 g_w1T_hi[(size_t)4 * DD * DD];
__device__ __nv_bfloat16 g_w1T_lo[(size_t)4 * DD * DD];
__device__ __nv_bfloat16 g_w2T_hi[(size_t)4 * DD * DD];
__device__ __nv_bfloat16 g_w2T_lo[(size_t)4 * DD * DD];

// ---------------- weight transpose + hi/lo split:  w[K,N] -> wT_hi/lo[N,K] ----------------
__global__ void __launch_bounds__(256) wsplit_kernel(const float* __restrict__ w,
                                                     __nv_bfloat16* __restrict__ thi,
                                                     __nv_bfloat16* __restrict__ tlo,
                                                     int K, int N) {
    __shared__ float t[32][33];
    int tx = threadIdx.x, ty = threadIdx.y;
    int n0 = blockIdx.x * 32, k0 = blockIdx.y * 32;
    #pragma unroll
    for (int r = 0; r < 32; r += 8)
        t[ty + r][tx] = w[(size_t)(k0 + ty + r) * N + n0 + tx];
    __syncthreads();
    #pragma unroll
    for (int r = 0; r < 32; r += 8) {
        int n = n0 + ty + r;
        int k = k0 + tx;
        float v = t[tx][ty + r];
        __nv_bfloat16 hi = __float2bfloat16(v);
        thi[(size_t)n * K + k] = hi;
        tlo[(size_t)n * K + k] = __float2bfloat16(v - __bfloat162float(hi));
    }
}

// ---------------- LayerNorm -> bf16 hi/lo ----------------
__global__ void __launch_bounds__(256) ln_kernel(const float* __restrict__ x,
                                                 const float* __restrict__ g,
                                                 const float* __restrict__ b,
                                                 __nv_bfloat16* __restrict__ yhi,
                                                 __nv_bfloat16* __restrict__ ylo) {
    int row = blockIdx.x;
    int tid = threadIdx.x;
    const float4* xr = (const float4*)(x + (size_t)row * DD);
    float4 v = xr[tid];
    float s  = v.x + v.y + v.z + v.w;
    float sq = v.x*v.x + v.y*v.y + v.z*v.z + v.w*v.w;
    #pragma unroll
    for (int off = 16; off > 0; off >>= 1) {
        s  += __shfl_xor_sync(0xffffffff, s,  off);
        sq += __shfl_xor_sync(0xffffffff, sq, off);
    }
    __shared__ float ss[8], ssq[8];
    __shared__ float smu, srstd;
    int wid = tid >> 5, lane = tid & 31;
    if (lane == 0) { ss[wid] = s; ssq[wid] = sq; }
    __syncthreads();
    if (tid == 0) {
        float t = 0.f, t2 = 0.f;
        #pragma unroll
        for (int w = 0; w < 8; ++w) { t += ss[w]; t2 += ssq[w]; }
        float mu  = t * (1.0f / DD);
        float var = t2 * (1.0f / DD) - mu * mu;
        smu = mu; srstd = rsqrtf(var + 1e-5f);
    }
    __syncthreads();
    float mu = smu, rstd = srstd;
    float4 gg = ((const float4*)g)[tid];
    float4 bb = ((const float4*)b)[tid];
    float o0 = (v.x - mu) * rstd * gg.x + bb.x;
    float o1 = (v.y - mu) * rstd * gg.y + bb.y;
    float o2 = (v.z - mu) * rstd * gg.z + bb.z;
    float o3 = (v.w - mu) * rstd * gg.w + bb.w;
    __nv_bfloat16 h0 = __float2bfloat16(o0), h1 = __float2bfloat16(o1);
    __nv_bfloat16 h2 = __float2bfloat16(o2), h3 = __float2bfloat16(o3);
    union { __nv_bfloat162 h[2]; uint2 u; } ph, pl;
    ph.h[0].x = h0; ph.h[0].y = h1; ph.h[1].x = h2; ph.h[1].y = h3;
    pl.h[0].x = __float2bfloat16(o0 - __bfloat162float(h0));
    pl.h[0].y = __float2bfloat16(o1 - __bfloat162float(h1));
    pl.h[1].x = __float2bfloat16(o2 - __bfloat162float(h2));
    pl.h[1].y = __float2bfloat16(o3 - __bfloat162float(h3));
    *(uint2*)&yhi[(size_t)row * DD + tid * 4] = ph.u;
    *(uint2*)&ylo[(size_t)row * DD + tid * 4] = pl.u;
}

// ---------------- bf16x3 mma.sync GEMM: C[M,N] = A[M,K] @ B[N,K]^T ----------------
// EPI: 0 bias->fp32 | 1 bias+res->fp32 | 2 bias+GELU->bf16 hi/lo | 3 bias+res->fp32
#define BM 128
#define BN 128
#define BKK 32
#define SROW 40                        // padded row stride (bf16) -> conflict-free ldmatrix
#define MAT_ELEMS (128 * SROW)         // 5120 bf16 per matrix
#define STAGE_ELEMS (4 * MAT_ELEMS)    // Ahi, Alo, Bhi, Blo
#define NSTG 3
#define GEMM_SMEM_B (NSTG * STAGE_ELEMS * 2)   // 122880 bytes

__device__ __forceinline__ void load_stage(
    uint32_t sbase, int s, int it,
    const __nv_bfloat16* __restrict__ Ahi, const __nv_bfloat16* __restrict__ Alo,
    const __nv_bfloat16* __restrict__ Bhi, const __nv_bfloat16* __restrict__ Blo,
    int m0, int n0, int K, int row_a, int col8)
{
    int kk = it * BKK;
    uint32_t sb = sbase + (uint32_t)s * (STAGE_ELEMS * 2);
    size_t ga0 = (size_t)(m0 + row_a) * K + kk + col8;
    size_t ga1 = (size_t)(m0 + row_a + 64) * K + kk + col8;
    size_t gb0 = (size_t)(n0 + row_a) * K + kk + col8;
    size_t gb1 = (size_t)(n0 + row_a + 64) * K + kk + col8;
    uint32_t s0 = (uint32_t)(row_a * SROW + col8) * 2;
    uint32_t s1 = (uint32_t)((row_a + 64) * SROW + col8) * 2;
    CP16(sb + s0, Ahi + ga0);                    CP16(sb + s1, Ahi + ga1);
    CP16(sb + MAT_ELEMS*2 + s0, Alo + ga0);      CP16(sb + MAT_ELEMS*2 + s1, Alo + ga1);
    CP16(sb + 2*MAT_ELEMS*2 + s0, Bhi + gb0);    CP16(sb + 2*MAT_ELEMS*2 + s1, Bhi + gb1);
    CP16(sb + 3*MAT_ELEMS*2 + s0, Blo + gb0);    CP16(sb + 3*MAT_ELEMS*2 + s1, Blo + gb1);
}

template<int EPI>
__global__ void __launch_bounds__(256) gemm_bf3(
    const __nv_bfloat16* __restrict__ Ahi, const __nv_bfloat16* __restrict__ Alo,
    const __nv_bfloat16* __restrict__ Bhi, const __nv_bfloat16* __restrict__ Blo,
    const float* __restrict__ bias, const float* __restrict__ res,
    float* __restrict__ C, __nv_bfloat16* __restrict__ Ohi, __nv_bfloat16* __restrict__ Olo,
    int M, int N, int K)
{
    extern __shared__ __nv_bfloat16 smem[];
    const int tid = threadIdx.x;
    const int wid = tid >> 5, lane = tid & 31;
    const int m0 = blockIdx.y * BM, n0 = blockIdx.x * BN;
    const int warp_m = wid & 3;     // 4 warps over M (32 rows each)
    const int warp_n = wid >> 2;    // 2 warps over N (64 cols each)
    uint32_t sbase = smem_u32(smem);

    // gmem->smem load geometry: 512 16B-chunks per matrix, 2 per thread
    const int row_a = tid >> 2;
    const int col8  = (tid & 3) * 8;

    // ldmatrix lane address components (bf16 units)
    const int a_row = ((lane >> 3) & 1) * 8 + (lane & 7);
    const int a_col = (lane >> 4) * 8;
    const int b_row = (lane >> 4) * 8 + (lane & 7);
    const int b_col = ((lane >> 3) & 1) * 8;
    uint32_t aoff[2], boff[4];
    #pragma unroll
    for (int am = 0; am < 2; am++)
        aoff[am] = (uint32_t)((warp_m * 32 + am * 16 + a_row) * SROW + a_col);
    #pragma unroll
    for (int p = 0; p < 4; p++)
        boff[p] = (uint32_t)((warp_n * 64 + p * 16 + b_row) * SROW + b_col);

    float acc[2][8][4];
    #pragma unroll
    for (int am = 0; am < 2; am++)
        #pragma unroll
        for (int an = 0; an < 8; an++)
            #pragma unroll
            for (int q = 0; q < 4; q++) acc[am][an][q] = 0.f;

    const int nit = K / BKK;
    load_stage(sbase, 0, 0, Ahi, Alo, Bhi, Blo, m0, n0, K, row_a, col8); CP_COMMIT();
    load_stage(sbase, 1, 1, Ahi, Alo, Bhi, Blo, m0, n0, K, row_a, col8); CP_COMMIT();

    for (int i = 0; i < nit; i++) {
        CP_WAIT1();
        __syncthreads();
        if (i + 2 < nit)
            load_stage(sbase, (i + 2) % NSTG, i + 2, Ahi, Alo, Bhi, Blo, m0, n0, K, row_a, col8);
        CP_COMMIT();

        uint32_t sb = sbase + (uint32_t)(i % NSTG) * (STAGE_ELEMS * 2);
        #pragma unroll
        for (int k0 = 0; k0 < BKK; k0 += 16) {
            uint32_t ah[2][4], al[2][4];
            #pragma unroll
            for (int am = 0; am < 2; am++) {
                LDSM4(ah[am], sb + (aoff[am] + k0) * 2);
                LDSM4(al[am], sb + (MAT_ELEMS + aoff[am] + k0) * 2);
            }
            #pragma unroll
            for (int p = 0; p < 4; p++) {
                uint32_t bh[4], bl[4];
                LDSM4(bh, sb + (2 * MAT_ELEMS + boff[p] + k0) * 2);
                LDSM4(bl, sb + (3 * MAT_ELEMS + boff[p] + k0) * 2);
                #pragma unroll
                for (int am = 0; am < 2; am++) {
                    MMA16816(acc[am][2*p],   ah[am], bh[0], bh[1]);
                    MMA16816(acc[am][2*p],   ah[am], bl[0], bl[1]);
                    MMA16816(acc[am][2*p],   al[am], bh[0], bh[1]);
                    MMA16816(acc[am][2*p+1], ah[am], bh[2], bh[3]);
                    MMA16816(acc[am][2*p+1], ah[am], bl[2], bl[3]);
                    MMA16816(acc[am][2*p+1], al[am], bh[2], bh[3]);
                }
            }
        }
    }

    // ---- epilogue: per-warp direct to gmem ----
    const int g = lane >> 2;
    const int tig2 = (lane & 3) * 2;
    #pragma unroll
    for (int am = 0; am < 2; am++) {
        #pragma unroll
        for (int an = 0; an < 8; an++) {
            int row = m0 + warp_m * 32 + am * 16 + g;
            int col = n0 + warp_n * 64 + an * 8 + tig2;
            float b0 = bias[col], b1 = bias[col + 1];
            #pragma unroll
            for (int h = 0; h < 2; h++) {
                int rr = row + h * 8;
                size_t off = (size_t)rr * N + col;
                float v0 = acc[am][an][2*h + 0] + b0;
                float v1 = acc[am][an][2*h + 1] + b1;
                if (EPI == 1 || EPI == 3) {
                    float2 rv = *(const float2*)(res + off);
                    v0 += rv.x; v1 += rv.y;
                }
                if (EPI == 2) {
                    v0 = 0.5f * v0 * (1.0f + erff(v0 * 0.70710678118654752f));
                    v1 = 0.5f * v1 * (1.0f + erff(v1 * 0.70710678118654752f));
                    __nv_bfloat16 h0 = __float2bfloat16(v0), h1 = __float2bfloat16(v1);
                    union { __nv_bfloat162 bh; uint32_t u; } ph, pl;
                    ph.bh.x = h0; ph.bh.y = h1;
                    pl.bh.x = __float2bfloat16(v0 - __bfloat162float(h0));
                    pl.bh.y = __float2bfloat16(v1 - __bfloat162float(h1));
                    ((uint32_t*)Ohi)[off >> 1] = ph.u;
                    ((uint32_t*)Olo)[off >> 1] = pl.u;
                } else {
                    *(float2*)(C + off) = make_float2(v0, v1);
                }
            }
        }
    }
}

// ---------------- Flash attention (fp32, online softmax, vectorized LDS) ----------------
#define SLD 68
#define ATTN_SMEM ((4 * 64 * SLD + 3 * 64) * (int)sizeof(float))

__global__ void __launch_bounds__(256) attn_kernel(const float* __restrict__ qkv,
                                                   __nv_bfloat16* __restrict__ ohi,
                                                   __nv_bfloat16* __restrict__ olo) {
    extern __shared__ float sm[];
    float* sQ  = sm;
    float* sK  = sQ + 64 * SLD;
    float* sV  = sK + 64 * SLD;
    float* sS  = sV + 64 * SLD;
    float* sM  = sS + 64 * SLD;
    float* sL  = sM + 64;
    float* sAl = sL + 64;

    int tid = threadIdx.x;
    int qt = blockIdx.x, bh = blockIdx.y;
    int b = bh >> 4, h = bh & 15;
    const size_t rs = 3 * DD;

    size_t qbase = ((size_t)(b * SS + qt * 64)) * rs + h * DH;
    #pragma unroll
    for (int t = 0; t < 4; t++) {
        int g = tid + t * 256; int r = g >> 4; int c4 = (g & 15) * 4;
        *(float4*)&sQ[r * SLD + c4] = *(const float4*)&qkv[qbase + (size_t)r * rs + c4];
    }
    if (tid < 64) { sM[tid] = -1e30f; sL[tid] = 0.f; }

    int qb = tid >> 4, dc = tid & 15;
    int q0 = qb * 4;
    float acc[4][4];
    #pragma unroll
    for (int i = 0; i < 4; i++)
        #pragma unroll
        for (int j = 0; j < 4; j++) acc[i][j] = 0.f;

    for (int kt = 0; kt < SS / 64; ++kt) {
        __syncthreads();
        size_t kbase = ((size_t)(b * SS + kt * 64)) * rs + h * DH;
        #pragma unroll
        for (int t = 0; t < 4; t++) {
            int g = tid + t * 256; int r = g >> 4; int c4 = (g & 15) * 4;
            size_t gg = kbase + (size_t)r * rs + c4;
            *(float4*)&sK[r * SLD + c4] = *(const float4*)&qkv[gg + DD];
            *(float4*)&sV[r * SLD + c4] = *(const float4*)&qkv[gg + 2 * DD];
        }
        __syncthreads();

        float s4[4][4];
        #pragma unroll
        for (int i = 0; i < 4; i++)
            #pragma unroll
            for (int j = 0; j < 4; j++) s4[i][j] = 0.f;
        #pragma unroll 4
        for (int d = 0; d < 64; d += 4) {
            float4 a[4];
            #pragma unroll
            for (int i = 0; i < 4; i++) a[i] = *(float4*)&sQ[(q0 + i) * SLD + d];
            #pragma unroll
            for (int jj = 0; jj < 4; jj++) {
                float4 kk4 = *(float4*)&sK[(dc + jj * 16) * SLD + d];
                #pragma unroll
                for (int i = 0; i < 4; i++) {
                    s4[i][jj] = fmaf(a[i].x, kk4.x, s4[i][jj]);
                    s4[i][jj] = fmaf(a[i].y, kk4.y, s4[i][jj]);
                    s4[i][jj] = fmaf(a[i].z, kk4.z, s4[i][jj]);
                    s4[i][jj] = fmaf(a[i].w, kk4.w, s4[i][jj]);
                }
            }
        }
        #pragma unroll
        for (int i = 0; i < 4; i++)
            #pragma unroll
            for (int jj = 0; jj < 4; jj++)
                sS[(q0 + i) * SLD + dc + jj * 16] = s4[i][jj] * 0.125f;
        __syncthreads();

        if (tid < 64) {
            float mold = sM[tid], mt = -1e30f;
            const float* row = sS + tid * SLD;
            #pragma unroll 16
            for (int k = 0; k < 64; k++) mt = fmaxf(mt, row[k]);
            float mnew = fmaxf(mold, mt);
            sAl[tid] = __expf(mold - mnew);
            sM[tid]  = mnew;
        }
        __syncthreads();

        #pragma unroll
        for (int i = 0; i < 4; i++) {
            float mn = sM[q0 + i], al = sAl[q0 + i];
            float4 p = *(float4*)&sS[(q0 + i) * SLD + dc * 4];
            p.x = __expf(p.x - mn); p.y = __expf(p.y - mn);
            p.z = __expf(p.z - mn); p.w = __expf(p.w - mn);
            *(float4*)&sS[(q0 + i) * SLD + dc * 4] = p;
            #pragma unroll
            for (int j = 0; j < 4; j++) acc[i][j] *= al;
        }
        __syncthreads();

        if (tid < 64) {
            float lsum = 0.f;
            const float* row = sS + tid * SLD;
            #pragma unroll 16
            for (int k = 0; k < 64; k++) lsum += row[k];
            sL[tid] = sL[tid] * sAl[tid] + lsum;
        }
        #pragma unroll 4
        for (int k = 0; k < 64; k += 4) {
            float pp[4][4];
            #pragma unroll
            for (int i = 0; i < 4; i++) *(float4*)pp[i] = *(float4*)&sS[(q0 + i) * SLD + k];
            #pragma unroll
            for (int kk = 0; kk < 4; kk++) {
                float4 vv = *(float4*)&sV[(k + kk) * SLD + dc * 4];
                #pragma unroll
                for (int i = 0; i < 4; i++) {
                    acc[i][0] = fmaf(pp[i][kk], vv.x, acc[i][0]);
                    acc[i][1] = fmaf(pp[i][kk], vv.y, acc[i][1]);
                    acc[i][2] = fmaf(pp[i][kk], vv.z, acc[i][2]);
                    acc[i][3] = fmaf(pp[i][kk], vv.w, acc[i][3]);
                }
            }
        }
    }
    __syncthreads();

    size_t obase = ((size_t)(b * SS + qt * 64)) * DD + h * DH;
    #pragma unroll
    for (int i = 0; i < 4; i++) {
        float inv = 1.0f / sL[q0 + i];
        float v0 = acc[i][0] * inv, v1 = acc[i][1] * inv;
        float v2 = acc[i][2] * inv, v3 = acc[i][3] * inv;
        __nv_bfloat16 h0 = __float2bfloat16(v0), h1 = __float2bfloat16(v1);
        __nv_bfloat16 h2 = __float2bfloat16(v2), h3 = __float2bfloat16(v3);
        union { __nv_bfloat162 hh[2]; uint2 u; } ph, pl;
        ph.hh[0].x = h0; ph.hh[0].y = h1; ph.hh[1].x = h2; ph.hh[1].y = h3;
        pl.hh[0].x = __float2bfloat16(v0 - __bfloat162float(h0));
        pl.hh[0].y = __float2bfloat16(v1 - __bfloat162float(h1));
        pl.hh[1].x = __float2bfloat16(v2 - __bfloat162float(h2));
        pl.hh[1].y = __float2bfloat16(v3 - __bfloat162float(h3));
        size_t addr = obase + (size_t)(q0 + i) * DD + dc * 4;
        *(uint2*)&ohi[addr] = ph.u;
        *(uint2*)&olo[addr] = pl.u;
    }
}

// ---------------- launch ----------------
extern "C" void kernel_launch(void* const* d_in, const int* in_sizes, int n_in,
                              void* d_out, int out_size) {
    const float* x     = (const float*)d_in[0];
    const float* ln1_g = (const float*)d_in[1];
    const float* ln1_b = (const float*)d_in[2];
    const float* w_qkv = (const float*)d_in[3];
    const float* b_qkv = (const float*)d_in[4];
    const float* w_out = (const float*)d_in[5];
    const float* b_out = (const float*)d_in[6];
    const float* ln2_g = (const float*)d_in[7];
    const float* ln2_b = (const float*)d_in[8];
    const float* w1    = (const float*)d_in[9];
    const float* b1    = (const float*)d_in[10];
    const float* w2    = (const float*)d_in[11];
    const float* b2    = (const float*)d_in[12];
    float* out = (float*)d_out;

    __nv_bfloat16 *h_hi, *h_lo, *att_hi, *att_lo, *ff_hi, *ff_lo;
    __nv_bfloat16 *wqkvT_hi, *wqkvT_lo, *woutT_hi, *woutT_lo, *w1T_hi, *w1T_lo, *w2T_hi, *w2T_lo;
    float *qkv, *x1;
    cudaGetSymbolAddress((void**)&h_hi, g_h_hi);     cudaGetSymbolAddress((void**)&h_lo, g_h_lo);
    cudaGetSymbolAddress((void**)&qkv, g_qkv);
    cudaGetSymbolAddress((void**)&att_hi, g_att_hi); cudaGetSymbolAddress((void**)&att_lo, g_att_lo);
    cudaGetSymbolAddress((void**)&x1, g_x1);
    cudaGetSymbolAddress((void**)&ff_hi, g_ff_hi);   cudaGetSymbolAddress((void**)&ff_lo, g_ff_lo);
    cudaGetSymbolAddress((void**)&wqkvT_hi, g_wqkvT_hi); cudaGetSymbolAddress((void**)&wqkvT_lo, g_wqkvT_lo);
    cudaGetSymbolAddress((void**)&woutT_hi, g_woutT_hi); cudaGetSymbolAddress((void**)&woutT_lo, g_woutT_lo);
    cudaGetSymbolAddress((void**)&w1T_hi, g_w1T_hi); cudaGetSymbolAddress((void**)&w1T_lo, g_w1T_lo);
    cudaGetSymbolAddress((void**)&w2T_hi, g_w2T_hi); cudaGetSymbolAddress((void**)&w2T_lo, g_w2T_lo);

    cudaFuncSetAttribute(attn_kernel, cudaFuncAttributeMaxDynamicSharedMemorySize, ATTN_SMEM);
    cudaFuncSetAttribute(gemm_bf3<0>, cudaFuncAttributeMaxDynamicSharedMemorySize, GEMM_SMEM_B);
    cudaFuncSetAttribute(gemm_bf3<1>, cudaFuncAttributeMaxDynamicSharedMemorySize, GEMM_SMEM_B);
    cudaFuncSetAttribute(gemm_bf3<2>, cudaFuncAttributeMaxDynamicSharedMemorySize, GEMM_SMEM_B);
    cudaFuncSetAttribute(gemm_bf3<3>, cudaFuncAttributeMaxDynamicSharedMemorySize, GEMM_SMEM_B);

    dim3 tb(32, 8);
    // weight transpose + split
    wsplit_kernel<<<dim3(3 * DD / 32, DD / 32), tb>>>(w_qkv, wqkvT_hi, wqkvT_lo, DD, 3 * DD);
    wsplit_kernel<<<dim3(DD / 32, DD / 32), tb>>>(w_out, woutT_hi, woutT_lo, DD, DD);
    wsplit_kernel<<<dim3(4 * DD / 32, DD / 32), tb>>>(w1, w1T_hi, w1T_lo, DD, 4 * DD);
    wsplit_kernel<<<dim3(DD / 32, 4 * DD / 32), tb>>>(w2, w2T_hi, w2T_lo, 4 * DD, DD);

    // LN1 -> bf16 hi/lo
    ln_kernel<<<MTOT, 256>>>(x, ln1_g, ln1_b, h_hi, h_lo);
    // QKV projection -> fp32
    gemm_bf3<0><<<dim3(3 * DD / BN, MTOT / BM), 256, GEMM_SMEM_B>>>(
        h_hi, h_lo, wqkvT_hi, wqkvT_lo, b_qkv, nullptr, qkv, nullptr, nullptr,
        MTOT, 3 * DD, DD);
    // Attention -> bf16 hi/lo
    attn_kernel<<<dim3(SS / 64, BB * HH), 256, ATTN_SMEM>>>(qkv, att_hi, att_lo);
    // Out projection + residual(x) -> x1 fp32
    gemm_bf3<1><<<dim3(DD / BN, MTOT / BM), 256, GEMM_SMEM_B>>>(
        att_hi, att_lo, woutT_hi, woutT_lo, b_out, x, x1, nullptr, nullptr,
        MTOT, DD, DD);
    // LN2 -> bf16 hi/lo
    ln_kernel<<<MTOT, 256>>>(x1, ln2_g, ln2_b, h_hi, h_lo);
    // MLP up + GELU -> bf16 hi/lo
    gemm_bf3<2><<<dim3(4 * DD / BN, MTOT / BM), 256, GEMM_SMEM_B>>>(
        h_hi, h_lo, w1T_hi, w1T_lo, b1, nullptr, nullptr, ff_hi, ff_lo,
        MTOT, 4 * DD, DD);
    // MLP down + residual(x1) -> final output
    gemm_bf3<3><<<dim3(DD / BN, MTOT / BM), 256, GEMM_SMEM_B>>>(
        ff_hi, ff_lo, w2T_hi, w2T_lo, b2, x1, out, nullptr, nullptr,
        MTOT, DD, 4 * DD);
}